// round 13
// baseline (speedup 1.0000x reference)
#include <cuda_runtime.h>
#include <cstdint>
#include <math.h>

// Problem: B=2,H=16,Q=4096,D=128,KV=10521,G=16,KP=1536,BM=256
#define NBH    32
#define QLEN   4096
#define DIM    128
#define KVLEN  10521
#define NG     16
#define KPAD   1536
#define QT     128           // q rows per CTA (2 CTAs per group)
#define KT     32
#define NTILES (KPAD / KT)   // 48
#define NTHR   256           // 8 warps; 2 CTAs/SM

// smem: Q 64KB | K 16KB (single) | VT 2x16KB (double) = 112KB per CTA
#define SQ   0
#define SK   (SQ + 128 * 512)         // 65536
#define SVT  (SK + 32 * 512)          // 81920
#define VBUF (128 * 128)              // 16384
#define SM_TOTAL (SVT + 2 * VBUF)     // 114688 B

// conflict-aware chunk swizzle: LDS.128 phase rows 2p,2p+1 get XORs differing in bit 2
__host__ __device__ __forceinline__ int swz(int r) { return ((r & 1) << 2) | (r >> 1); }

__device__ __forceinline__ uint32_t smem_u32(const void* p) {
    uint32_t a;
    asm("{ .reg .u64 t; cvta.to.shared.u64 t, %1; cvt.u32.u64 %0, t; }" : "=r"(a) : "l"(p));
    return a;
}
__device__ __forceinline__ uint32_t f2tf32(float x) {
    uint32_t r; asm("cvt.rna.tf32.f32 %0, %1;" : "=r"(r) : "f"(x)); return r;
}
__device__ __forceinline__ void cpa16(uint32_t dst, const void* src) {
    asm volatile("cp.async.cg.shared.global [%0], [%1], 16;" :: "r"(dst), "l"(src));
}
__device__ __forceinline__ void cpa4(uint32_t dst, const void* src) {
    asm volatile("cp.async.ca.shared.global [%0], [%1], 4;" :: "r"(dst), "l"(src));
}
#define CP_COMMIT() asm volatile("cp.async.commit_group;" ::: "memory")
#define CP_WAIT(n)  asm volatile("cp.async.wait_group %0;" :: "n"(n) : "memory")

__device__ __forceinline__ void mma_tf32(float* d, uint32_t a0, uint32_t a1,
                                         uint32_t a2, uint32_t a3,
                                         uint32_t b0, uint32_t b1) {
    asm volatile(
        "mma.sync.aligned.m16n8k8.row.col.f32.tf32.tf32.f32 "
        "{%0,%1,%2,%3}, {%4,%5,%6,%7}, {%8,%9}, {%0,%1,%2,%3};"
        : "+f"(d[0]), "+f"(d[1]), "+f"(d[2]), "+f"(d[3])
        : "r"(a0), "r"(a1), "r"(a2), "r"(a3), "r"(b0), "r"(b1));
}
__device__ __forceinline__ uint4 lds128(const char* p) {
    return *(const uint4*)p;
}
#define RNA 0x1000u   // +half-ulp of tf32 before HW truncation == round-nearest-away

__global__ void __launch_bounds__(NTHR, 2)
sparse_attn_mma(const float* __restrict__ q,
                const float* __restrict__ k,
                const float* __restrict__ v,
                const int*   __restrict__ inds,
                float*       __restrict__ out)
{
    extern __shared__ __align__(128) char sm[];
    const uint32_t sbu = smem_u32(sm);

    const int tid  = threadIdx.x;
    const int wid  = tid >> 5;      // 0..7
    const int lane = tid & 31;
    const int lq   = lane >> 2;     // 0..7
    const int lr   = lane & 3;      // 0..3

    const int bid = blockIdx.x;     // 0..1023
    const int qt  = bid & 1;
    const int g   = (bid >> 1) & 15;
    const int bh  = bid >> 5;
    const int qbase = g * 256 + qt * QT;

    const float* qp = q + ((size_t)bh * QLEN + qbase) * DIM;
    const float* kb = k + (size_t)bh * KVLEN * DIM;
    const float* vb = v + (size_t)bh * KVLEN * DIM;
    const int*   ib = inds + ((size_t)bh * NG + g) * KPAD;
    float*       op = out + ((size_t)bh * QLEN + qbase) * DIM;

    const float scale = 0.088388347648318447f;   // 1/sqrt(128)

    // K gather: 32 rows x 512B, coalesced 16B cp.async (1024 ops / 256 thr)
    #define ISSUE_K(tt) do {                                                      \
        const int* ibn = ib + (tt) * KT;                                          \
        _Pragma("unroll")                                                         \
        for (int i = 0; i < 4; ++i) {                                             \
            const int e = tid + i * NTHR;                                         \
            const int row = e >> 5, c = e & 31;                                   \
            const int gi = __ldg(ibn + row);                                      \
            cpa16(sbu + SK + row * 512 + ((16 * c) ^ (swz(row & 7) << 4)),        \
                  kb + (size_t)gi * DIM + 4 * c);                                 \
        }                                                                         \
    } while (0)

    // VT gather: 128 rows x 128B, kv sigma-permuted (S-accum regs == PV A-frag)
    #define ISSUE_V(tt, buf) do {                                                 \
        const int* ibn = ib + (tt) * KT;                                          \
        const uint32_t svn = sbu + SVT + (buf) * VBUF;                            \
        _Pragma("unroll")                                                         \
        for (int i = 0; i < 4; ++i) {                                             \
            const int p  = wid + 8 * i;             /* 0..31 */                   \
            const int rr = p & 7;                   /* chunk 0..7 */              \
            const int dd = (p >> 3) * 32 + lane;    /* d row 0..127 */            \
            const int sbase = 16 * (rr >> 2) + 2 * (rr & 3);                      \
            const uint32_t dbase = svn + dd * 128 +                               \
                ((16 * rr) ^ (swz(dd & 7) << 4));                                 \
            const int g0 = __ldg(ibn + sbase + 0);                                \
            const int g1 = __ldg(ibn + sbase + 1);                                \
            const int g2 = __ldg(ibn + sbase + 8);                                \
            const int g3 = __ldg(ibn + sbase + 9);                                \
            cpa4(dbase + 0,  vb + (size_t)g0 * DIM + dd);                         \
            cpa4(dbase + 4,  vb + (size_t)g1 * DIM + dd);                         \
            cpa4(dbase + 8,  vb + (size_t)g2 * DIM + dd);                         \
            cpa4(dbase + 12, vb + (size_t)g3 * DIM + dd);                         \
        }                                                                         \
    } while (0)

    // ---- prologue: start K(0), V(0); load Q (rna + pre-scale) meanwhile ----
    ISSUE_K(0);
    CP_COMMIT();
    ISSUE_V(0, 0);
    CP_COMMIT();

    #pragma unroll
    for (int i = 0; i < 16; ++i) {
        const int e   = tid + i * NTHR;
        const int row = e >> 5, c = e & 31;
        float4 val = ((const float4*)(qp + (size_t)row * DIM))[c];
        uint4 u;
        u.x = f2tf32(val.x * scale); u.y = f2tf32(val.y * scale);
        u.z = f2tf32(val.z * scale); u.w = f2tf32(val.w * scale);
        *(uint4*)(sm + SQ + row * 512 + ((16 * c) ^ (swz(row & 7) << 4))) = u;
    }

    // per-thread constant addressing (warp owns q rows wid*16 .. wid*16+15)
    const int xorA  = swz(lq) << 4;
    const char* rbA0 = sm + SQ + (wid * 16 + lq) * 512;
    const char* rbA1 = rbA0 + 8 * 512;
    const int  xorB  = swz(lq) << 4;
    const char* rbK = sm + SK + lq * 512;

    float oacc[16][4];
    #pragma unroll
    for (int j = 0; j < 16; ++j)
        #pragma unroll
        for (int c = 0; c < 4; ++c) oacc[j][c] = 0.0f;
    float l0 = 0.0f, l1 = 0.0f;   // per-lane partials; reduced in epilogue

    for (int t = 0; t < NTILES; ++t) {
        CP_WAIT(1);          // K(t) landed (V(t) may still be in flight)
        __syncthreads();

        // ---- QK: S[16 x 32] per warp; conflict-free lds128 frags; rna K ----
        float sacc[4][4];
        #pragma unroll
        for (int j = 0; j < 4; ++j)
            #pragma unroll
            for (int c = 0; c < 4; ++c) sacc[j][c] = 0.0f;

        #pragma unroll
        for (int pr = 0; pr < 8; ++pr) {
            const int abyte = (64 * pr + 16 * lr) ^ xorA;
            const uint4 A0 = lds128(rbA0 + abyte);
            const uint4 A1 = lds128(rbA1 + abyte);
            const int bbyte = (64 * pr + 16 * lr) ^ xorB;
            #pragma unroll
            for (int j = 0; j < 4; ++j) {
                uint4 B = lds128(rbK + j * (8 * 512) + bbyte);
                B.x += RNA; B.y += RNA; B.z += RNA; B.w += RNA;
                mma_tf32(sacc[j], A0.x, A1.x, A0.y, A1.y, B.x, B.y);
                mma_tf32(sacc[j], A0.z, A1.z, A0.w, A1.w, B.z, B.w);
            }
        }
        __syncthreads();     // all warps done reading K(t)
        if (t + 1 < NTILES) { ISSUE_K(t + 1); CP_COMMIT(); }

        // ---- softmax: exp, per-lane partial sums, P -> regs (PV A-frag order) ----
        uint32_t* pf = reinterpret_cast<uint32_t*>(&sacc[0][0]);
        #pragma unroll
        for (int j = 0; j < 4; ++j) {
            const float e0 = __expf(fminf(sacc[j][0], 60.0f));
            const float e1 = __expf(fminf(sacc[j][1], 60.0f));
            const float e2 = __expf(fminf(sacc[j][2], 60.0f));
            const float e3 = __expf(fminf(sacc[j][3], 60.0f));
            l0 += e0 + e1;  l1 += e2 + e3;
            pf[4 * j + 0] = f2tf32(e0);   // a0: row lq,   k-slot lr
            pf[4 * j + 1] = f2tf32(e2);   // a1: row lq+8, k-slot lr
            pf[4 * j + 2] = f2tf32(e1);   // a2: row lq,   k-slot lr+4
            pf[4 * j + 3] = f2tf32(e3);   // a3: row lq+8, k-slot lr+4
        }

        // ---- wait V(t); PV: O[16 x 128] += P x V ; P from regs; V truncates ----
        if (t + 1 < NTILES) { CP_WAIT(1); } else { CP_WAIT(0); }
        __syncthreads();

        const char* rbV = sm + SVT + (t & 1) * VBUF + lq * 128;
        #pragma unroll
        for (int prl = 0; prl < 2; ++prl) {
            const int vbyte = (64 * prl + 16 * lr) ^ xorB;
            const uint32_t* pa = pf + 8 * prl;
            #pragma unroll
            for (int j = 0; j < 16; ++j) {
                const uint4 B = lds128(rbV + j * (8 * 128) + vbyte);
                mma_tf32(oacc[j], pa[0], pa[1], pa[2], pa[3], B.x, B.y);
                mma_tf32(oacc[j], pa[4], pa[5], pa[6], pa[7], B.z, B.w);
            }
        }
        __syncthreads();     // all warps done reading VT(t)
        if (t + 1 < NTILES) { ISSUE_V(t + 1, (t + 1) & 1); CP_COMMIT(); }
    }

    // ---- epilogue: reduce row sums across lr group, divide, store ----
    l0 += __shfl_xor_sync(0xffffffffu, l0, 1);
    l0 += __shfl_xor_sync(0xffffffffu, l0, 2);
    l1 += __shfl_xor_sync(0xffffffffu, l1, 1);
    l1 += __shfl_xor_sync(0xffffffffu, l1, 2);
    const float inv0 = 1.0f / l0;
    const float inv1 = 1.0f / l1;
    float* orow0 = op + (size_t)(wid * 16 + lq) * DIM;
    float* orow1 = orow0 + 8 * DIM;
    #pragma unroll
    for (int j = 0; j < 16; ++j) {
        const int col = 8 * j + 2 * lr;
        float2 r0, r1;
        r0.x = oacc[j][0] * inv0;  r0.y = oacc[j][1] * inv0;
        r1.x = oacc[j][2] * inv1;  r1.y = oacc[j][3] * inv1;
        *(float2*)(orow0 + col) = r0;
        *(float2*)(orow1 + col) = r1;
    }
}

extern "C" void kernel_launch(void* const* d_in, const int* in_sizes, int n_in,
                              void* d_out, int out_size)
{
    const float* q    = (const float*)d_in[0];
    const float* k    = (const float*)d_in[1];
    const float* v    = (const float*)d_in[2];
    const int*   inds = (const int*)d_in[3];
    float*       out  = (float*)d_out;

    cudaFuncSetAttribute(sparse_attn_mma,
                         cudaFuncAttributeMaxDynamicSharedMemorySize, SM_TOTAL);

    const int grid = NBH * NG * 2;   // 1024 CTAs, 2 resident per SM
    sparse_attn_mma<<<grid, NTHR, SM_TOTAL>>>(q, k, v, inds, out);
}

// round 14
// speedup vs baseline: 1.1302x; 1.1302x over previous
#include <cuda_runtime.h>
#include <cstdint>
#include <math.h>

// Problem: B=2,H=16,Q=4096,D=128,KV=10521,G=16,KP=1536,BM=256
#define NBH    32
#define QLEN   4096
#define DIM    128
#define KVLEN  10521
#define NG     16
#define KPAD   1536
#define QT     256           // whole query group per CTA
#define KT     64
#define NTILES (KPAD / KT)   // 24
#define NTHR   256           // 8 warps, 32 q-rows each

// smem: Q 128KB | K 32KB (single) | VT 2x32KB (double) = 224KB
#define SQ   0
#define SK   (SQ  + 256 * 512)
#define SVT  (SK  + 64 * 512)
#define VBUF 32768
#define SM_TOTAL (SVT + 2 * VBUF)     // 229376 B

// conflict-aware chunk swizzle
__host__ __device__ __forceinline__ int swz(int r) { return ((r & 1) << 2) | (r >> 1); }

__device__ __forceinline__ uint32_t smem_u32(const void* p) {
    uint32_t a;
    asm("{ .reg .u64 t; cvta.to.shared.u64 t, %1; cvt.u32.u64 %0, t; }" : "=r"(a) : "l"(p));
    return a;
}
__device__ __forceinline__ uint32_t f2tf32(float x) {
    uint32_t r; asm("cvt.rna.tf32.f32 %0, %1;" : "=r"(r) : "f"(x)); return r;
}
__device__ __forceinline__ void cpa16(uint32_t dst, const void* src) {
    asm volatile("cp.async.cg.shared.global [%0], [%1], 16;" :: "r"(dst), "l"(src));
}
__device__ __forceinline__ void cpa4(uint32_t dst, const void* src) {
    asm volatile("cp.async.ca.shared.global [%0], [%1], 4;" :: "r"(dst), "l"(src));
}
#define CP_COMMIT() asm volatile("cp.async.commit_group;" ::: "memory")
#define CP_WAIT(n)  asm volatile("cp.async.wait_group %0;" :: "n"(n) : "memory")

__device__ __forceinline__ void mma_tf32(float* d, uint32_t a0, uint32_t a1,
                                         uint32_t a2, uint32_t a3,
                                         uint32_t b0, uint32_t b1) {
    asm volatile(
        "mma.sync.aligned.m16n8k8.row.col.f32.tf32.tf32.f32 "
        "{%0,%1,%2,%3}, {%4,%5,%6,%7}, {%8,%9}, {%0,%1,%2,%3};"
        : "+f"(d[0]), "+f"(d[1]), "+f"(d[2]), "+f"(d[3])
        : "r"(a0), "r"(a1), "r"(a2), "r"(a3), "r"(b0), "r"(b1));
}
__device__ __forceinline__ uint4 lds128(const char* p) {
    return *(const uint4*)p;
}
#define RNA 0x1000u

__global__ void __launch_bounds__(NTHR, 1)
sparse_attn_mma(const float* __restrict__ q,
                const float* __restrict__ k,
                const float* __restrict__ v,
                const int*   __restrict__ inds,
                float*       __restrict__ out)
{
    extern __shared__ __align__(128) char sm[];
    const uint32_t sbu = smem_u32(sm);

    const int tid  = threadIdx.x;
    const int wid  = tid >> 5;      // 0..7
    const int lane = tid & 31;
    const int lq   = lane >> 2;     // 0..7
    const int lr   = lane & 3;      // 0..3

    const int bid = blockIdx.x;     // 0..511
    const int g   = bid & 15;
    const int bh  = bid >> 4;
    const int qbase = g * 256;

    const float* qp = q + ((size_t)bh * QLEN + qbase) * DIM;
    const float* kb = k + (size_t)bh * KVLEN * DIM;
    const float* vb = v + (size_t)bh * KVLEN * DIM;
    const int*   ib = inds + ((size_t)bh * NG + g) * KPAD;
    float*       op = out + ((size_t)bh * QLEN + qbase) * DIM;

    const float scale = 0.088388347648318447f;   // 1/sqrt(128)

    // K gather: 64 rows x 512B, coalesced 16B cp.async
    #define ISSUE_K(tt) do {                                                      \
        const int* ibn = ib + (tt) * KT;                                          \
        _Pragma("unroll")                                                         \
        for (int i = 0; i < 8; ++i) {                                             \
            const int e = tid + i * NTHR;                                         \
            const int row = e >> 5, c = e & 31;                                   \
            const int gi = __ldg(ibn + row);                                      \
            cpa16(sbu + SK + row * 512 + ((16 * c) ^ (swz(row & 7) << 4)),        \
                  kb + (size_t)gi * DIM + 4 * c);                                 \
        }                                                                         \
    } while (0)

    // VT gather: 128 rows x 256B, kv sigma-permuted (S-accum regs == PV A-frag)
    #define ISSUE_V(tt, buf) do {                                                 \
        const int* ibn = ib + (tt) * KT;                                          \
        const uint32_t svn = sbu + SVT + (buf) * VBUF;                            \
        _Pragma("unroll")                                                         \
        for (int i = 0; i < 8; ++i) {                                             \
            const int p  = wid + 8 * i;                                           \
            const int rr = p & 15;                                                \
            const int dd = (p >> 4) * 32 + lane;                                  \
            const int sbase = 16 * (rr >> 2) + 2 * (rr & 3);                      \
            const uint32_t dbase = svn + dd * 256 +                               \
                (((16 * rr) & 0x7F) ^ (swz(dd & 7) << 4)) + ((16 * rr) & 0x80);   \
            const int g0 = __ldg(ibn + sbase + 0);                                \
            const int g1 = __ldg(ibn + sbase + 1);                                \
            const int g2 = __ldg(ibn + sbase + 8);                                \
            const int g3 = __ldg(ibn + sbase + 9);                                \
            cpa4(dbase + 0,  vb + (size_t)g0 * DIM + dd);                         \
            cpa4(dbase + 4,  vb + (size_t)g1 * DIM + dd);                         \
            cpa4(dbase + 8,  vb + (size_t)g2 * DIM + dd);                         \
            cpa4(dbase + 12, vb + (size_t)g3 * DIM + dd);                         \
        }                                                                         \
    } while (0)

    // ---- prologue ----
    ISSUE_K(0);
    CP_COMMIT();
    ISSUE_V(0, 0);
    CP_COMMIT();

    #pragma unroll
    for (int i = 0; i < 32; ++i) {
        const int e   = tid + i * NTHR;
        const int row = e >> 5, c = e & 31;
        float4 val = ((const float4*)(qp + (size_t)row * DIM))[c];
        uint4 u;
        u.x = f2tf32(val.x * scale); u.y = f2tf32(val.y * scale);
        u.z = f2tf32(val.z * scale); u.w = f2tf32(val.w * scale);
        *(uint4*)(sm + SQ + row * 512 + ((16 * c) ^ (swz(row & 7) << 4))) = u;
    }

    // warp owns q rows wid*32 .. wid*32+31
    const int xorA  = swz(lq) << 4;
    const char* rbA0 = sm + SQ + (wid * 32 + lq) * 512;
    const char* rbA1 = rbA0 + 8 * 512;
    const char* rbA2 = rbA0 + 16 * 512;
    const char* rbA3 = rbA0 + 24 * 512;
    const int  xorB  = swz(lq) << 4;
    const char* rbK = sm + SK + lq * 512;

    float oacc[2][16][4];
    #pragma unroll
    for (int m = 0; m < 2; ++m)
        #pragma unroll
        for (int j = 0; j < 16; ++j)
            #pragma unroll
            for (int c = 0; c < 4; ++c) oacc[m][j][c] = 0.0f;
    float l0 = 0.0f, l1 = 0.0f, l2 = 0.0f, l3 = 0.0f;  // per-lane partials

    for (int t = 0; t < NTILES; ++t) {
        CP_WAIT(1);          // drain K(t); V(t) may still be in flight
        __syncthreads();

        const char* rbV = sm + SVT + (t & 1) * VBUF + lq * 256;

        #pragma unroll
        for (int h = 0; h < 2; ++h) {
            // ---- QK half: S[32 x 32], K row-groups 4h..4h+3 ----
            float sacc[2][4][4];
            #pragma unroll
            for (int m = 0; m < 2; ++m)
                #pragma unroll
                for (int j = 0; j < 4; ++j)
                    #pragma unroll
                    for (int c = 0; c < 4; ++c) sacc[m][j][c] = 0.0f;

            #pragma unroll
            for (int pr = 0; pr < 8; ++pr) {
                const int abyte = (64 * pr + 16 * lr) ^ xorA;
                const uint4 A0 = lds128(rbA0 + abyte);
                const uint4 A1 = lds128(rbA1 + abyte);
                const uint4 A2 = lds128(rbA2 + abyte);
                const uint4 A3 = lds128(rbA3 + abyte);
                const int bbyte = (64 * pr + 16 * lr) ^ xorB;
                #pragma unroll
                for (int j = 0; j < 4; ++j) {
                    uint4 B = lds128(rbK + (4 * h + j) * (8 * 512) + bbyte);
                    B.x += RNA; B.y += RNA; B.z += RNA; B.w += RNA;
                    mma_tf32(sacc[0][j], A0.x, A1.x, A0.y, A1.y, B.x, B.y);
                    mma_tf32(sacc[0][j], A0.z, A1.z, A0.w, A1.w, B.z, B.w);
                    mma_tf32(sacc[1][j], A2.x, A3.x, A2.y, A3.y, B.x, B.y);
                    mma_tf32(sacc[1][j], A2.z, A3.z, A2.w, A3.w, B.z, B.w);
                }
            }

            // ---- softmax half: exp, partial sums, P -> regs (PV A-frag order) ----
            uint32_t* pf = reinterpret_cast<uint32_t*>(&sacc[0][0][0]);
            #pragma unroll
            for (int j = 0; j < 4; ++j) {
                const float e0 = __expf(fminf(sacc[0][j][0], 60.0f));
                const float e1 = __expf(fminf(sacc[0][j][1], 60.0f));
                const float e2 = __expf(fminf(sacc[0][j][2], 60.0f));
                const float e3 = __expf(fminf(sacc[0][j][3], 60.0f));
                l0 += e0 + e1;  l1 += e2 + e3;
                pf[4 * j + 0] = f2tf32(e0);
                pf[4 * j + 1] = f2tf32(e2);
                pf[4 * j + 2] = f2tf32(e1);
                pf[4 * j + 3] = f2tf32(e3);
                const float f0 = __expf(fminf(sacc[1][j][0], 60.0f));
                const float f1 = __expf(fminf(sacc[1][j][1], 60.0f));
                const float f2 = __expf(fminf(sacc[1][j][2], 60.0f));
                const float f3 = __expf(fminf(sacc[1][j][3], 60.0f));
                l2 += f0 + f1;  l3 += f2 + f3;
                pf[16 + 4 * j + 0] = f2tf32(f0);
                pf[16 + 4 * j + 1] = f2tf32(f2);
                pf[16 + 4 * j + 2] = f2tf32(f1);
                pf[16 + 4 * j + 3] = f2tf32(f3);
            }

            if (h == 0) {
                CP_WAIT(0);       // drain V(t) (only group outstanding here)
                __syncthreads();  // V(t) visible to all warps
            }

            // ---- PV half: O[32 x 128] += P_h x V (kv groups 2h, 2h+1) ----
            #pragma unroll
            for (int prl = 0; prl < 2; ++prl) {
                const int vv = 64 * (2 * h + prl) + 16 * lr;
                const int vbyte = ((vv & 0x7F) ^ xorB) + (vv & 0x80);
                const uint32_t* pa0 = pf + 8 * prl;
                const uint32_t* pa1 = pf + 16 + 8 * prl;
                #pragma unroll
                for (int j = 0; j < 16; ++j) {
                    const uint4 B = lds128(rbV + j * (8 * 256) + vbyte);
                    mma_tf32(oacc[0][j], pa0[0], pa0[1], pa0[2], pa0[3], B.x, B.y);
                    mma_tf32(oacc[0][j], pa0[4], pa0[5], pa0[6], pa0[7], B.z, B.w);
                    mma_tf32(oacc[1][j], pa1[0], pa1[1], pa1[2], pa1[3], B.x, B.y);
                    mma_tf32(oacc[1][j], pa1[4], pa1[5], pa1[6], pa1[7], B.z, B.w);
                }
            }

            if (h == 0) {
                // after PV-h0 comes QK-h1 (K reads), so K still in use; nothing here
            } else {
                __syncthreads();   // all warps done reading K(t) and VT(t)
                if (t + 1 < NTILES) {
                    ISSUE_K(t + 1); CP_COMMIT();
                    ISSUE_V(t + 1, (t + 1) & 1); CP_COMMIT();
                }
            }
        }
    }

    // ---- epilogue: reduce row sums, divide, store ----
    l0 += __shfl_xor_sync(0xffffffffu, l0, 1);
    l0 += __shfl_xor_sync(0xffffffffu, l0, 2);
    l1 += __shfl_xor_sync(0xffffffffu, l1, 1);
    l1 += __shfl_xor_sync(0xffffffffu, l1, 2);
    l2 += __shfl_xor_sync(0xffffffffu, l2, 1);
    l2 += __shfl_xor_sync(0xffffffffu, l2, 2);
    l3 += __shfl_xor_sync(0xffffffffu, l3, 1);
    l3 += __shfl_xor_sync(0xffffffffu, l3, 2);
    const float i0 = 1.0f / l0, i1 = 1.0f / l1, i2 = 1.0f / l2, i3 = 1.0f / l3;
    {
        float* r0 = op + (size_t)(wid * 32 + lq) * DIM;
        float* r1 = r0 + 8 * DIM;
        float* r2 = r0 + 16 * DIM;
        float* r3 = r0 + 24 * DIM;
        #pragma unroll
        for (int j = 0; j < 16; ++j) {
            const int col = 8 * j + 2 * lr;
            float2 a, b, c, d;
            a.x = oacc[0][j][0] * i0;  a.y = oacc[0][j][1] * i0;
            b.x = oacc[0][j][2] * i1;  b.y = oacc[0][j][3] * i1;
            c.x = oacc[1][j][0] * i2;  c.y = oacc[1][j][1] * i2;
            d.x = oacc[1][j][2] * i3;  d.y = oacc[1][j][3] * i3;
            *(float2*)(r0 + col) = a;
            *(float2*)(r1 + col) = b;
            *(float2*)(r2 + col) = c;
            *(float2*)(r3 + col) = d;
        }
    }
}

extern "C" void kernel_launch(void* const* d_in, const int* in_sizes, int n_in,
                              void* d_out, int out_size)
{
    const float* q    = (const float*)d_in[0];
    const float* k    = (const float*)d_in[1];
    const float* v    = (const float*)d_in[2];
    const int*   inds = (const int*)d_in[3];
    float*       out  = (float*)d_out;

    cudaFuncSetAttribute(sparse_attn_mma,
                         cudaFuncAttributeMaxDynamicSharedMemorySize, SM_TOTAL);

    const int grid = NBH * NG;   // 512
    sparse_attn_mma<<<grid, NTHR, SM_TOTAL>>>(q, k, v, inds, out);
}

// round 15
// speedup vs baseline: 1.5108x; 1.3368x over previous
#include <cuda_runtime.h>
#include <cstdint>
#include <math.h>

// Problem: B=2,H=16,Q=4096,D=128,KV=10521,G=16,KP=1536,BM=256
#define NBH    32
#define QLEN   4096
#define DIM    128
#define KVLEN  10521
#define NG     16
#define KPAD   1536
#define QT     256
#define KT     64
#define NTILES (KPAD / KT)   // 24
#define NTHR   256

// smem layout (bytes)
#define SQ16 0                      // Q fp16: 256 rows x 256B = 64KB
#define SKS  (SQ16 + 256 * 256)     // K fp32 staging: 64 x 512B = 32KB
#define SVS  (SKS  + 64 * 512)      // V fp32 staging (transposed): 128 x 256B = 32KB
#define SK16 (SVS  + 128 * 256)     // K fp16: 64 x 256B = 16KB
#define SV16 (SK16 + 64 * 256)      // VT fp16: 128 x 128B = 16KB
#define SM_TOTAL (SV16 + 128 * 128) // 163840 B

__host__ __device__ __forceinline__ int swz(int r) { return ((r & 1) << 2) | (r >> 1); }
// fp16 granule (2 fp16, natural k = 2g,2g+1) byte placement within a row:
// block s = g>>3 (32B), pairs (lr, lr+4) adjacent at 8*lr
__device__ __forceinline__ int gbyte(int g) {
    return 32 * (g >> 3) + 8 * (g & 3) + (((g >> 2) & 1) << 2);
}

__device__ __forceinline__ uint32_t smem_u32(const void* p) {
    uint32_t a;
    asm("{ .reg .u64 t; cvta.to.shared.u64 t, %1; cvt.u32.u64 %0, t; }" : "=r"(a) : "l"(p));
    return a;
}
__device__ __forceinline__ uint32_t pack_h2(float lo, float hi) {
    uint32_t r; asm("cvt.rn.f16x2.f32 %0, %1, %2;" : "=r"(r) : "f"(hi), "f"(lo)); return r;
}
__device__ __forceinline__ void cpa16(uint32_t dst, const void* src) {
    asm volatile("cp.async.cg.shared.global [%0], [%1], 16;" :: "r"(dst), "l"(src));
}
__device__ __forceinline__ void cpa4(uint32_t dst, const void* src) {
    asm volatile("cp.async.ca.shared.global [%0], [%1], 4;" :: "r"(dst), "l"(src));
}
#define CP_COMMIT() asm volatile("cp.async.commit_group;" ::: "memory")
#define CP_WAIT(n)  asm volatile("cp.async.wait_group %0;" :: "n"(n) : "memory")

__device__ __forceinline__ void mma_f16(float* d, uint32_t a0, uint32_t a1,
                                        uint32_t a2, uint32_t a3,
                                        uint32_t b0, uint32_t b1) {
    asm volatile(
        "mma.sync.aligned.m16n8k16.row.col.f32.f16.f16.f32 "
        "{%0,%1,%2,%3}, {%4,%5,%6,%7}, {%8,%9}, {%0,%1,%2,%3};"
        : "+f"(d[0]), "+f"(d[1]), "+f"(d[2]), "+f"(d[3])
        : "r"(a0), "r"(a1), "r"(a2), "r"(a3), "r"(b0), "r"(b1));
}
__device__ __forceinline__ uint4 lds128(const char* p) { return *(const uint4*)p; }
__device__ __forceinline__ uint2 lds64(const char* p)  { return *(const uint2*)p; }

__global__ void __launch_bounds__(NTHR, 1)
sparse_attn_f16(const float* __restrict__ q,
                const float* __restrict__ k,
                const float* __restrict__ v,
                const int*   __restrict__ inds,
                float*       __restrict__ out)
{
    extern __shared__ __align__(128) char sm[];
    const uint32_t sbu = smem_u32(sm);

    const int tid  = threadIdx.x;
    const int wid  = tid >> 5;      // 0..7
    const int lane = tid & 31;
    const int lq   = lane >> 2;     // 0..7
    const int lr   = lane & 3;      // 0..3
    const int xr   = (lq & 3) << 5; // bank swizzle for all fp16 row reads

    const int bid = blockIdx.x;     // 0..511
    const int g   = bid & 15;
    const int bh  = bid >> 4;
    const int qbase = g * 256;

    const float* qp = q + ((size_t)bh * QLEN + qbase) * DIM;
    const float* kb = k + (size_t)bh * KVLEN * DIM;
    const float* vb = v + (size_t)bh * KVLEN * DIM;
    const int*   ib = inds + ((size_t)bh * NG + g) * KPAD;
    float*       op = out + ((size_t)bh * QLEN + qbase) * DIM;

    const float scale = 0.088388347648318447f;   // 1/sqrt(128)

    // K gather -> fp32 staging (64 x 512B, chunk^swz layout)
    #define ISSUE_K(tt) do {                                                      \
        const int* ibn = ib + (tt) * KT;                                          \
        _Pragma("unroll")                                                         \
        for (int i = 0; i < 8; ++i) {                                             \
            const int e = tid + i * NTHR;                                         \
            const int row = e >> 5, c = e & 31;                                   \
            const int gi = __ldg(ibn + row);                                      \
            cpa16(sbu + SKS + row * 512 + ((16 * c) ^ (swz(row & 7) << 4)),       \
                  kb + (size_t)gi * DIM + 4 * c);                                 \
        }                                                                         \
    } while (0)

    // V gather (transposed) -> fp32 staging (128 x 256B, natural kv order)
    #define ISSUE_V(tt) do {                                                      \
        const int* ibn = ib + (tt) * KT;                                          \
        _Pragma("unroll")                                                         \
        for (int i = 0; i < 8; ++i) {                                             \
            const int p  = wid + 8 * i;             /* 0..63 */                   \
            const int rr = p & 15;                  /* chunk: kv 4rr..4rr+3 */    \
            const int dd = (p >> 4) * 32 + lane;                                  \
            const uint32_t dbase = sbu + SVS + dd * 256 +                         \
                (((16 * rr) & 0x7F) ^ (swz(dd & 7) << 4)) + ((16 * rr) & 0x80);   \
            const int g0 = __ldg(ibn + 4 * rr + 0);                               \
            const int g1 = __ldg(ibn + 4 * rr + 1);                               \
            const int g2 = __ldg(ibn + 4 * rr + 2);                               \
            const int g3 = __ldg(ibn + 4 * rr + 3);                               \
            cpa4(dbase + 0,  vb + (size_t)g0 * DIM + dd);                         \
            cpa4(dbase + 4,  vb + (size_t)g1 * DIM + dd);                         \
            cpa4(dbase + 8,  vb + (size_t)g2 * DIM + dd);                         \
            cpa4(dbase + 12, vb + (size_t)g3 * DIM + dd);                         \
        }                                                                         \
    } while (0)

    // ---- prologue: start K(0), V(0); convert Q -> fp16 meanwhile ----
    ISSUE_K(0);
    CP_COMMIT();
    ISSUE_V(0);
    CP_COMMIT();

    #pragma unroll
    for (int i = 0; i < 32; ++i) {
        const int e   = tid + i * NTHR;
        const int row = e >> 5, c = e & 31;
        const float4 val = ((const float4*)(qp + (size_t)row * DIM))[c];
        const uint32_t plo = pack_h2(val.x * scale, val.y * scale);
        const uint32_t phi = pack_h2(val.z * scale, val.w * scale);
        char* dst = sm + SQ16 + row * 256;
        const int X = (row & 3) << 5;
        *(uint32_t*)(dst + (gbyte(2 * c)     ^ X)) = plo;
        *(uint32_t*)(dst + (gbyte(2 * c + 1) ^ X)) = phi;
    }

    // warp-private pointers (warp owns q rows wid*32 .. wid*32+31)
    const char* rbA = sm + SQ16 + (wid * 32 + lq) * 256;   // +roff*256
    const char* rbK = sm + SK16 + lq * 256;                // + j*8*256
    const char* rbV = sm + SV16 + lq * 128;                // + j*8*128

    float oacc[2][16][4];
    #pragma unroll
    for (int m = 0; m < 2; ++m)
        #pragma unroll
        for (int j = 0; j < 16; ++j)
            #pragma unroll
            for (int c = 0; c < 4; ++c) oacc[m][j][c] = 0.0f;
    float l0 = 0.0f, l1 = 0.0f, l2 = 0.0f, l3 = 0.0f;

    for (int t = 0; t < NTILES; ++t) {
        CP_WAIT(1);          // K(t) staged (V(t) may be pending)
        __syncthreads();     // also: all warps finished compute of tile t-1

        // ---- convert K: fp32 staging -> fp16 tile ----
        {
            const int qr = tid >> 6, row = tid & 63;
            const char* src = sm + SKS + row * 512;
            uint32_t pk16[16];
            #pragma unroll
            for (int i = 0; i < 8; ++i) {
                const uint4 vv = lds128(src + 16 * ((8 * qr + i) ^ swz(row & 7)));
                pk16[2 * i]     = pack_h2(__uint_as_float(vv.x), __uint_as_float(vv.y));
                pk16[2 * i + 1] = pack_h2(__uint_as_float(vv.z), __uint_as_float(vv.w));
            }
            char* dst = sm + SK16 + row * 256;
            const int X = (row & 3) << 5;
            *(uint4*)(dst + ((64 * qr +  0) ^ X)) = make_uint4(pk16[0], pk16[4],  pk16[1],  pk16[5]);
            *(uint4*)(dst + ((64 * qr + 16) ^ X)) = make_uint4(pk16[2], pk16[6],  pk16[3],  pk16[7]);
            *(uint4*)(dst + ((64 * qr + 32) ^ X)) = make_uint4(pk16[8], pk16[12], pk16[9],  pk16[13]);
            *(uint4*)(dst + ((64 * qr + 48) ^ X)) = make_uint4(pk16[10], pk16[14], pk16[11], pk16[15]);
        }
        CP_WAIT(0);          // V(t) staged
        __syncthreads();     // K16 visible; V staging visible

        // ---- convert V: fp32 staging -> fp16 tile ----
        {
            const int half = tid >> 7, row = tid & 127;
            const char* src = sm + SVS + row * 256 + 128 * half;
            uint32_t pk16[16];
            #pragma unroll
            for (int i = 0; i < 8; ++i) {
                const uint4 vv = lds128(src + 16 * (i ^ swz(row & 7)));
                pk16[2 * i]     = pack_h2(__uint_as_float(vv.x), __uint_as_float(vv.y));
                pk16[2 * i + 1] = pack_h2(__uint_as_float(vv.z), __uint_as_float(vv.w));
            }
            char* dst = sm + SV16 + row * 128;
            const int X = (row & 3) << 5;
            *(uint4*)(dst + ((64 * half +  0) ^ X)) = make_uint4(pk16[0], pk16[4],  pk16[1],  pk16[5]);
            *(uint4*)(dst + ((64 * half + 16) ^ X)) = make_uint4(pk16[2], pk16[6],  pk16[3],  pk16[7]);
            *(uint4*)(dst + ((64 * half + 32) ^ X)) = make_uint4(pk16[8], pk16[12], pk16[9],  pk16[13]);
            *(uint4*)(dst + ((64 * half + 48) ^ X)) = make_uint4(pk16[10], pk16[14], pk16[11], pk16[15]);
        }
        __syncthreads();     // K16/V16 ready; both stagings free

        if (t + 1 < NTILES) {
            ISSUE_K(t + 1); CP_COMMIT();
            ISSUE_V(t + 1); CP_COMMIT();
        }

        // ---- compute in two kv halves (register pressure control) ----
        #pragma unroll
        for (int h = 0; h < 2; ++h) {
            // QK half: S[32 x 32], n-tiles j = 4h..4h+3, 8 k-steps of 16
            float sacc[2][4][4];
            #pragma unroll
            for (int m = 0; m < 2; ++m)
                #pragma unroll
                for (int j = 0; j < 4; ++j)
                    #pragma unroll
                    for (int c = 0; c < 4; ++c) sacc[m][j][c] = 0.0f;

            #pragma unroll
            for (int s = 0; s < 8; ++s) {
                const int fb = (32 * s + 8 * lr) ^ xr;
                const uint2 A00 = lds64(rbA + 0 * 256  + fb);   // m0 row lq   : a0,a2
                const uint2 A01 = lds64(rbA + 8 * 256  + fb);   // m0 row lq+8 : a1,a3
                const uint2 A10 = lds64(rbA + 16 * 256 + fb);   // m1
                const uint2 A11 = lds64(rbA + 24 * 256 + fb);
                #pragma unroll
                for (int jl = 0; jl < 4; ++jl) {
                    const uint2 B = lds64(rbK + (4 * h + jl) * (8 * 256) + fb);
                    mma_f16(sacc[0][jl], A00.x, A01.x, A00.y, A01.y, B.x, B.y);
                    mma_f16(sacc[1][jl], A10.x, A11.x, A10.y, A11.y, B.x, B.y);
                }
            }

            // softmax half: exp (clamp 11 for fp16 range), sums, pack P -> fp16 regs
            uint32_t pk0[8], pk1[8];
            #pragma unroll
            for (int jl = 0; jl < 4; ++jl) {
                const int base = (jl >> 1) * 4 + (jl & 1) * 2;
                {
                    const float e0 = __expf(fminf(sacc[0][jl][0], 11.0f));
                    const float e1 = __expf(fminf(sacc[0][jl][1], 11.0f));
                    const float e2 = __expf(fminf(sacc[0][jl][2], 11.0f));
                    const float e3 = __expf(fminf(sacc[0][jl][3], 11.0f));
                    l0 += e0 + e1;  l1 += e2 + e3;
                    pk0[base]     = pack_h2(e0, e1);
                    pk0[base + 1] = pack_h2(e2, e3);
                }
                {
                    const float e0 = __expf(fminf(sacc[1][jl][0], 11.0f));
                    const float e1 = __expf(fminf(sacc[1][jl][1], 11.0f));
                    const float e2 = __expf(fminf(sacc[1][jl][2], 11.0f));
                    const float e3 = __expf(fminf(sacc[1][jl][3], 11.0f));
                    l2 += e0 + e1;  l3 += e2 + e3;
                    pk1[base]     = pack_h2(e0, e1);
                    pk1[base + 1] = pack_h2(e2, e3);
                }
            }

            // PV half: O[32 x 128] += P_h x V ; kv k-blocks 2h, 2h+1
            #pragma unroll
            for (int kbl = 0; kbl < 2; ++kbl) {
                const int fb = (32 * (2 * h + kbl) + 8 * lr) ^ xr;
                const uint32_t* pa0 = pk0 + 4 * kbl;
                const uint32_t* pa1 = pk1 + 4 * kbl;
                #pragma unroll
                for (int j = 0; j < 16; ++j) {
                    const uint2 B = lds64(rbV + j * (8 * 128) + fb);
                    mma_f16(oacc[0][j], pa0[0], pa0[1], pa0[2], pa0[3], B.x, B.y);
                    mma_f16(oacc[1][j], pa1[0], pa1[1], pa1[2], pa1[3], B.x, B.y);
                }
            }
        }
    }

    // ---- epilogue: reduce row sums across lr group, divide, store ----
    l0 += __shfl_xor_sync(0xffffffffu, l0, 1);
    l0 += __shfl_xor_sync(0xffffffffu, l0, 2);
    l1 += __shfl_xor_sync(0xffffffffu, l1, 1);
    l1 += __shfl_xor_sync(0xffffffffu, l1, 2);
    l2 += __shfl_xor_sync(0xffffffffu, l2, 1);
    l2 += __shfl_xor_sync(0xffffffffu, l2, 2);
    l3 += __shfl_xor_sync(0xffffffffu, l3, 1);
    l3 += __shfl_xor_sync(0xffffffffu, l3, 2);
    const float i0 = 1.0f / l0, i1 = 1.0f / l1, i2 = 1.0f / l2, i3 = 1.0f / l3;
    {
        float* r0 = op + (size_t)(wid * 32 + lq) * DIM;
        float* r1 = r0 + 8 * DIM;
        float* r2 = r0 + 16 * DIM;
        float* r3 = r0 + 24 * DIM;
        #pragma unroll
        for (int j = 0; j < 16; ++j) {
            const int col = 8 * j + 2 * lr;
            float2 a, b, c, d;
            a.x = oacc[0][j][0] * i0;  a.y = oacc[0][j][1] * i0;
            b.x = oacc[0][j][2] * i1;  b.y = oacc[0][j][3] * i1;
            c.x = oacc[1][j][0] * i2;  c.y = oacc[1][j][1] * i2;
            d.x = oacc[1][j][2] * i3;  d.y = oacc[1][j][3] * i3;
            *(float2*)(r0 + col) = a;
            *(float2*)(r1 + col) = b;
            *(float2*)(r2 + col) = c;
            *(float2*)(r3 + col) = d;
        }
    }
}

extern "C" void kernel_launch(void* const* d_in, const int* in_sizes, int n_in,
                              void* d_out, int out_size)
{
    const float* q    = (const float*)d_in[0];
    const float* k    = (const float*)d_in[1];
    const float* v    = (const float*)d_in[2];
    const int*   inds = (const int*)d_in[3];
    float*       out  = (float*)d_out;

    cudaFuncSetAttribute(sparse_attn_f16,
                         cudaFuncAttributeMaxDynamicSharedMemorySize, SM_TOTAL);

    const int grid = NBH * NG;   // 512
    sparse_attn_f16<<<grid, NTHR, SM_TOTAL>>>(q, k, v, inds, out);
}

// round 16
// speedup vs baseline: 1.5487x; 1.0251x over previous
#include <cuda_runtime.h>
#include <cstdint>
#include <math.h>

// Problem: B=2,H=16,Q=4096,D=128,KV=10521,G=16,KP=1536,BM=256
#define NBH    32
#define QLEN   4096
#define DIM    128
#define KVLEN  10521
#define NG     16
#define KPAD   1536
#define QT     128            // q rows per CTA (2 CTAs per group)
#define KT     64
#define NTILES (KPAD / KT)    // 24
#define NTHR   256            // 8 warps; 2 CTAs per SM

// smem (bytes): Q16 32KB | K16 16KB | V16 16KB | VS staging 32KB = 96KB/CTA
#define SQ16 0
#define SK16 (SQ16 + 128 * 256)      // 32768
#define SV16 (SK16 + 64 * 256)       // 49152
#define SVS  (SV16 + 128 * 128)      // 65536
#define SM_TOTAL (SVS + 128 * 256)   // 98304 B

__host__ __device__ __forceinline__ int swz(int r) { return ((r & 1) << 2) | (r >> 1); }
// fp16 granule (2 fp16, k = 2g,2g+1) byte placement within a row
__device__ __forceinline__ int gbyte(int g) {
    return 32 * (g >> 3) + 8 * (g & 3) + (((g >> 2) & 1) << 2);
}

__device__ __forceinline__ uint32_t smem_u32(const void* p) {
    uint32_t a;
    asm("{ .reg .u64 t; cvta.to.shared.u64 t, %1; cvt.u32.u64 %0, t; }" : "=r"(a) : "l"(p));
    return a;
}
__device__ __forceinline__ uint32_t pack_h2(float lo, float hi) {
    uint32_t r; asm("cvt.rn.f16x2.f32 %0, %1, %2;" : "=r"(r) : "f"(hi), "f"(lo)); return r;
}
__device__ __forceinline__ void cpa4(uint32_t dst, const void* src) {
    asm volatile("cp.async.ca.shared.global [%0], [%1], 4;" :: "r"(dst), "l"(src));
}
#define CP_COMMIT() asm volatile("cp.async.commit_group;" ::: "memory")
#define CP_WAIT(n)  asm volatile("cp.async.wait_group %0;" :: "n"(n) : "memory")

__device__ __forceinline__ void mma_f16(float* d, uint32_t a0, uint32_t a1,
                                        uint32_t a2, uint32_t a3,
                                        uint32_t b0, uint32_t b1) {
    asm volatile(
        "mma.sync.aligned.m16n8k16.row.col.f32.f16.f16.f32 "
        "{%0,%1,%2,%3}, {%4,%5,%6,%7}, {%8,%9}, {%0,%1,%2,%3};"
        : "+f"(d[0]), "+f"(d[1]), "+f"(d[2]), "+f"(d[3])
        : "r"(a0), "r"(a1), "r"(a2), "r"(a3), "r"(b0), "r"(b1));
}
__device__ __forceinline__ uint4 lds128(const char* p) { return *(const uint4*)p; }
__device__ __forceinline__ uint2 lds64(const char* p)  { return *(const uint2*)p; }

__global__ void __launch_bounds__(NTHR, 2)
sparse_attn_f16(const float* __restrict__ q,
                const float* __restrict__ k,
                const float* __restrict__ v,
                const int*   __restrict__ inds,
                float*       __restrict__ out)
{
    extern __shared__ __align__(128) char sm[];
    const uint32_t sbu = smem_u32(sm);

    const int tid  = threadIdx.x;
    const int wid  = tid >> 5;      // 0..7
    const int lane = tid & 31;
    const int lq   = lane >> 2;     // 0..7
    const int lr   = lane & 3;      // 0..3
    const int xr   = (lq & 3) << 5; // bank swizzle for all fp16 row reads

    const int bid = blockIdx.x;     // 0..1023
    const int qt  = bid & 1;
    const int g   = (bid >> 1) & 15;
    const int bh  = bid >> 5;
    const int qbase = g * 256 + qt * QT;

    const float* qp = q + ((size_t)bh * QLEN + qbase) * DIM;
    const float* kb = k + (size_t)bh * KVLEN * DIM;
    const float* vb = v + (size_t)bh * KVLEN * DIM;
    const int*   ib = inds + ((size_t)bh * NG + g) * KPAD;
    float*       op = out + ((size_t)bh * QLEN + qbase) * DIM;

    const float scale = 0.088388347648318447f;   // 1/sqrt(128)

    // V gather (transposed) -> fp32 staging (128 x 256B)
    #define ISSUE_V(tt) do {                                                      \
        const int* ibn = ib + (tt) * KT;                                          \
        _Pragma("unroll")                                                         \
        for (int i = 0; i < 8; ++i) {                                             \
            const int p  = wid + 8 * i;             /* 0..63 */                   \
            const int rr = p & 15;                  /* kv chunk 4rr..4rr+3 */     \
            const int dd = (p >> 4) * 32 + lane;                                  \
            const uint32_t dbase = sbu + SVS + dd * 256 +                         \
                (((16 * rr) & 0x7F) ^ (swz(dd & 7) << 4)) + ((16 * rr) & 0x80);   \
            const int g0 = __ldg(ibn + 4 * rr + 0);                               \
            const int g1 = __ldg(ibn + 4 * rr + 1);                               \
            const int g2 = __ldg(ibn + 4 * rr + 2);                               \
            const int g3 = __ldg(ibn + 4 * rr + 3);                               \
            cpa4(dbase + 0,  vb + (size_t)g0 * DIM + dd);                         \
            cpa4(dbase + 4,  vb + (size_t)g1 * DIM + dd);                         \
            cpa4(dbase + 8,  vb + (size_t)g2 * DIM + dd);                         \
            cpa4(dbase + 12, vb + (size_t)g3 * DIM + dd);                         \
        }                                                                         \
    } while (0)

    // ---- prologue: start V(0); convert Q -> fp16 meanwhile ----
    ISSUE_V(0);
    CP_COMMIT();

    #pragma unroll
    for (int i = 0; i < 16; ++i) {
        const int e   = tid + i * NTHR;
        const int row = e >> 5, c = e & 31;
        const float4 val = ((const float4*)(qp + (size_t)row * DIM))[c];
        const uint32_t plo = pack_h2(val.x * scale, val.y * scale);
        const uint32_t phi = pack_h2(val.z * scale, val.w * scale);
        char* dst = sm + SQ16 + row * 256;
        const int X = (row & 3) << 5;
        *(uint32_t*)(dst + (gbyte(2 * c)     ^ X)) = plo;
        *(uint32_t*)(dst + (gbyte(2 * c + 1) ^ X)) = phi;
    }

    // warp-private pointers (warp owns q rows wid*16+lq, +8)
    const char* rbA = sm + SQ16 + (wid * 16 + lq) * 256;
    const char* rbK = sm + SK16 + lq * 256;    // + j*8*256
    const char* rbV = sm + SV16 + lq * 128;    // + j*8*128

    float oacc[16][4];
    #pragma unroll
    for (int j = 0; j < 16; ++j)
        #pragma unroll
        for (int c = 0; c < 4; ++c) oacc[j][c] = 0.0f;
    float l0 = 0.0f, l1 = 0.0f;   // per-lane partials

    for (int t = 0; t < NTILES; ++t) {
        CP_WAIT(0);          // VS(t) staged
        __syncthreads();     // and all warps done computing tile t-1

        // ---- gather K(t): LDG -> fp16 -> K16 (warp reads one row: gi uniform) ----
        {
            const int* ibn = ib + t * KT;
            #pragma unroll
            for (int i = 0; i < 8; ++i) {
                const int e = tid + i * NTHR;
                const int row = e >> 5, c = e & 31;
                const int gi = __ldg(ibn + row);
                const float4 val = ((const float4*)(kb + (size_t)gi * DIM))[c];
                char* dst = sm + SK16 + row * 256;
                const int X = (row & 3) << 5;
                *(uint32_t*)(dst + (gbyte(2 * c)     ^ X)) = pack_h2(val.x, val.y);
                *(uint32_t*)(dst + (gbyte(2 * c + 1) ^ X)) = pack_h2(val.z, val.w);
            }
        }

        // ---- convert V: fp32 staging -> fp16 tile (verified R15 mapping) ----
        {
            const int half = tid >> 7, row = tid & 127;
            const char* src = sm + SVS + row * 256 + 128 * half;
            uint32_t pk16[16];
            #pragma unroll
            for (int i = 0; i < 8; ++i) {
                const uint4 vv = lds128(src + 16 * (i ^ swz(row & 7)));
                pk16[2 * i]     = pack_h2(__uint_as_float(vv.x), __uint_as_float(vv.y));
                pk16[2 * i + 1] = pack_h2(__uint_as_float(vv.z), __uint_as_float(vv.w));
            }
            char* dst = sm + SV16 + row * 128;
            const int X = (row & 3) << 5;
            *(uint4*)(dst + ((64 * half +  0) ^ X)) = make_uint4(pk16[0],  pk16[4],  pk16[1],  pk16[5]);
            *(uint4*)(dst + ((64 * half + 16) ^ X)) = make_uint4(pk16[2],  pk16[6],  pk16[3],  pk16[7]);
            *(uint4*)(dst + ((64 * half + 32) ^ X)) = make_uint4(pk16[8],  pk16[12], pk16[9],  pk16[13]);
            *(uint4*)(dst + ((64 * half + 48) ^ X)) = make_uint4(pk16[10], pk16[14], pk16[11], pk16[15]);
        }
        __syncthreads();     // K16/V16 ready; VS free

        if (t + 1 < NTILES) { ISSUE_V(t + 1); CP_COMMIT(); }

        // ---- QK: S[16 x 64], 8 k-steps of 16 ----
        float sacc[8][4];
        #pragma unroll
        for (int j = 0; j < 8; ++j)
            #pragma unroll
            for (int c = 0; c < 4; ++c) sacc[j][c] = 0.0f;

        #pragma unroll
        for (int s = 0; s < 8; ++s) {
            const int fb = (32 * s + 8 * lr) ^ xr;
            const uint2 A0 = lds64(rbA + fb);            // row lq   : a0,a2
            const uint2 A1 = lds64(rbA + 8 * 256 + fb);  // row lq+8 : a1,a3
            #pragma unroll
            for (int j = 0; j < 8; ++j) {
                const uint2 B = lds64(rbK + j * (8 * 256) + fb);
                mma_f16(sacc[j], A0.x, A1.x, A0.y, A1.y, B.x, B.y);
            }
        }

        // ---- softmax: exp (clamp 11), per-lane sums, pack P -> fp16 regs ----
        uint32_t pk[16];
        #pragma unroll
        for (int j = 0; j < 8; ++j) {
            const float e0 = __expf(fminf(sacc[j][0], 11.0f));
            const float e1 = __expf(fminf(sacc[j][1], 11.0f));
            const float e2 = __expf(fminf(sacc[j][2], 11.0f));
            const float e3 = __expf(fminf(sacc[j][3], 11.0f));
            l0 += e0 + e1;  l1 += e2 + e3;
            pk[2 * j]     = pack_h2(e0, e1);   // row lq   granule (cols 8j+2lr,+1)
            pk[2 * j + 1] = pack_h2(e2, e3);   // row lq+8 granule
        }

        // ---- PV: O[16 x 128] += P x V ; 4 k-blocks of 16 kv ----
        #pragma unroll
        for (int kbl = 0; kbl < 4; ++kbl) {
            const int fb = (32 * kbl + 8 * lr) ^ xr;
            const uint32_t* pa = pk + 4 * kbl;
            #pragma unroll
            for (int j = 0; j < 16; ++j) {
                const uint2 B = lds64(rbV + j * (8 * 128) + fb);
                mma_f16(oacc[j], pa[0], pa[1], pa[2], pa[3], B.x, B.y);
            }
        }
    }

    // ---- epilogue: reduce row sums across lr group, divide, store ----
    l0 += __shfl_xor_sync(0xffffffffu, l0, 1);
    l0 += __shfl_xor_sync(0xffffffffu, l0, 2);
    l1 += __shfl_xor_sync(0xffffffffu, l1, 1);
    l1 += __shfl_xor_sync(0xffffffffu, l1, 2);
    const float inv0 = 1.0f / l0;
    const float inv1 = 1.0f / l1;
    float* orow0 = op + (size_t)(wid * 16 + lq) * DIM;
    float* orow1 = orow0 + 8 * DIM;
    #pragma unroll
    for (int j = 0; j < 16; ++j) {
        const int col = 8 * j + 2 * lr;
        float2 r0, r1;
        r0.x = oacc[j][0] * inv0;  r0.y = oacc[j][1] * inv0;
        r1.x = oacc[j][2] * inv1;  r1.y = oacc[j][3] * inv1;
        *(float2*)(orow0 + col) = r0;
        *(float2*)(orow1 + col) = r1;
    }
}

extern "C" void kernel_launch(void* const* d_in, const int* in_sizes, int n_in,
                              void* d_out, int out_size)
{
    const float* q    = (const float*)d_in[0];
    const float* k    = (const float*)d_in[1];
    const float* v    = (const float*)d_in[2];
    const int*   inds = (const int*)d_in[3];
    float*       out  = (float*)d_out;

    cudaFuncSetAttribute(sparse_attn_f16,
                         cudaFuncAttributeMaxDynamicSharedMemorySize, SM_TOTAL);

    const int grid = NBH * NG * 2;   // 1024 CTAs, 2 resident per SM
    sparse_attn_f16<<<grid, NTHR, SM_TOTAL>>>(q, k, v, inds, out);
}